// round 1
// baseline (speedup 1.0000x reference)
#include <cuda_runtime.h>
#include <math.h>

#define D_MODEL 2048
#define N_EXP   64
#define TOPK    2
#define TM      128          // tokens per CTA
#define BK      32           // k-slice per stage
#define NT      (D_MODEL / BK)   // 64 k-stages
#define THREADS 256
#define XSTR    129          // xs row stride (conflict-free: 129 % 32 == 1)
#define WSTR    65           // ws row stride (65 % 32 == 1)
#define SMEM_FLOATS (2*BK*XSTR + 2*BK*WSTR)

__global__ __launch_bounds__(THREADS, 2)
void router_kernel(const float* __restrict__ x,
                   const float* __restrict__ W,
                   const float* __restrict__ bias,
                   float* __restrict__ out, int T)
{
    __shared__ float smem[SMEM_FLOATS];
    float* xs = smem;                       // [2][BK][XSTR]  (k-major, token minor)
    float* ws = smem + 2 * BK * XSTR;       // [2][BK][WSTR]  (k-major, expert minor)

    const int tid = threadIdx.x;
    const int t0  = blockIdx.x * TM;
    const int tt  = tid & 15;    // token lane: handles tokens tt + 16*j, j=0..7
    const int ee  = tid >> 4;    // expert group: experts 4*ee .. 4*ee+3

    float bfrag[4];
#pragma unroll
    for (int u = 0; u < 4; ++u) bfrag[u] = bias[4 * ee + u];

    float acc[8][4];
#pragma unroll
    for (int j = 0; j < 8; ++j)
#pragma unroll
        for (int u = 0; u < 4; ++u) acc[j][u] = 0.0f;

    float4 xreg[4];
    float4 wreg[2];

    // ---- prologue: load k-stage 0 into regs, park in smem buf 0 ----
    {
        const int kt = 0;
#pragma unroll
        for (int i = 0; i < 4; ++i) {
            int v = tid + THREADS * i;
            int row = v >> 3, c4 = v & 7;
            xreg[i] = *reinterpret_cast<const float4*>(
                x + (size_t)(t0 + row) * D_MODEL + kt * BK + c4 * 4);
        }
#pragma unroll
        for (int i = 0; i < 2; ++i) {
            int v = tid + THREADS * i;
            int e = v >> 3, c4 = v & 7;
            wreg[i] = *reinterpret_cast<const float4*>(
                W + (size_t)e * D_MODEL + kt * BK + c4 * 4);
        }
        float* xb = xs;   // buf 0
#pragma unroll
        for (int i = 0; i < 4; ++i) {
            int v = tid + THREADS * i;
            int row = v >> 3, c4 = v & 7;
            xb[(c4 * 4 + 0) * XSTR + row] = xreg[i].x;
            xb[(c4 * 4 + 1) * XSTR + row] = xreg[i].y;
            xb[(c4 * 4 + 2) * XSTR + row] = xreg[i].z;
            xb[(c4 * 4 + 3) * XSTR + row] = xreg[i].w;
        }
        float* wb = ws;   // buf 0
#pragma unroll
        for (int i = 0; i < 2; ++i) {
            int v = tid + THREADS * i;
            int e = v >> 3, c4 = v & 7;
            wb[(c4 * 4 + 0) * WSTR + e] = wreg[i].x;
            wb[(c4 * 4 + 1) * WSTR + e] = wreg[i].y;
            wb[(c4 * 4 + 2) * WSTR + e] = wreg[i].z;
            wb[(c4 * 4 + 3) * WSTR + e] = wreg[i].w;
        }
    }
    __syncthreads();

    // ---- mainloop: double-buffered via registers + 2 smem stages ----
    for (int kt = 0; kt < NT; ++kt) {
        if (kt + 1 < NT) {
            const int kn = kt + 1;
#pragma unroll
            for (int i = 0; i < 4; ++i) {
                int v = tid + THREADS * i;
                int row = v >> 3, c4 = v & 7;
                xreg[i] = *reinterpret_cast<const float4*>(
                    x + (size_t)(t0 + row) * D_MODEL + kn * BK + c4 * 4);
            }
#pragma unroll
            for (int i = 0; i < 2; ++i) {
                int v = tid + THREADS * i;
                int e = v >> 3, c4 = v & 7;
                wreg[i] = *reinterpret_cast<const float4*>(
                    W + (size_t)e * D_MODEL + kn * BK + c4 * 4);
            }
        }

        {
            const float* xb = xs + (kt & 1) * (BK * XSTR);
            const float* wb = ws + (kt & 1) * (BK * WSTR);
#pragma unroll 4
            for (int k = 0; k < BK; ++k) {
                float xv[8], wv[4];
#pragma unroll
                for (int j = 0; j < 8; ++j) xv[j] = xb[k * XSTR + tt + 16 * j];
#pragma unroll
                for (int u = 0; u < 4; ++u) wv[u] = wb[k * WSTR + 4 * ee + u];
#pragma unroll
                for (int j = 0; j < 8; ++j)
#pragma unroll
                    for (int u = 0; u < 4; ++u)
                        acc[j][u] = fmaf(xv[j], wv[u], acc[j][u]);
            }
        }

        if (kt + 1 < NT) {
            const int nb = (kt + 1) & 1;
            float* xb = xs + nb * (BK * XSTR);
#pragma unroll
            for (int i = 0; i < 4; ++i) {
                int v = tid + THREADS * i;
                int row = v >> 3, c4 = v & 7;
                xb[(c4 * 4 + 0) * XSTR + row] = xreg[i].x;
                xb[(c4 * 4 + 1) * XSTR + row] = xreg[i].y;
                xb[(c4 * 4 + 2) * XSTR + row] = xreg[i].z;
                xb[(c4 * 4 + 3) * XSTR + row] = xreg[i].w;
            }
            float* wb = ws + nb * (BK * WSTR);
#pragma unroll
            for (int i = 0; i < 2; ++i) {
                int v = tid + THREADS * i;
                int e = v >> 3, c4 = v & 7;
                wb[(c4 * 4 + 0) * WSTR + e] = wreg[i].x;
                wb[(c4 * 4 + 1) * WSTR + e] = wreg[i].y;
                wb[(c4 * 4 + 2) * WSTR + e] = wreg[i].z;
                wb[(c4 * 4 + 3) * WSTR + e] = wreg[i].w;
            }
        }
        __syncthreads();
    }

    // ---- epilogue: gather logits (+bias) into smem, softmax + top-2 ----
    // reuse smem: logits[TM][WSTR] needs 128*65 = 8320 floats <= SMEM_FLOATS
    float* logits = smem;
#pragma unroll
    for (int j = 0; j < 8; ++j)
#pragma unroll
        for (int u = 0; u < 4; ++u)
            logits[(tt + 16 * j) * WSTR + (4 * ee + u)] = acc[j][u] + bfrag[u];
    __syncthreads();

    if (tid < TM) {
        const float* lrow = logits + tid * WSTR;
        float m1 = -INFINITY, m2 = -INFINITY;
        int   i1 = 0,         i2 = 0;
#pragma unroll 8
        for (int e = 0; e < N_EXP; ++e) {
            float l = lrow[e];
            if (l > m1) { m2 = m1; i2 = i1; m1 = l; i1 = e; }
            else if (l > m2) { m2 = l; i2 = e; }
        }
        float s = 0.0f;
#pragma unroll 8
        for (int e = 0; e < N_EXP; ++e) s += __expf(lrow[e] - m1);
        float inv = 1.0f / s;

        int tg = t0 + tid;
        // output layout: [top_idx (B*S*K) as float | top_w (B*S*K)]
        out[2 * tg + 0] = (float)i1;
        out[2 * tg + 1] = (float)i2;
        out[(size_t)2 * T + 2 * tg + 0] = inv;                    // exp(m1-m1)/Z
        out[(size_t)2 * T + 2 * tg + 1] = __expf(m2 - m1) * inv;  // exp(m2-m1)/Z
    }
}

extern "C" void kernel_launch(void* const* d_in, const int* in_sizes, int n_in,
                              void* d_out, int out_size)
{
    const float* x = (const float*)d_in[0];
    const float* W = (const float*)d_in[1];
    const float* b = (const float*)d_in[2];
    float* out = (float*)d_out;

    int T = in_sizes[0] / D_MODEL;   // 32768 tokens
    dim3 grid(T / TM);
    router_kernel<<<grid, THREADS>>>(x, W, b, out, T);
}

// round 6
// speedup vs baseline: 1.0328x; 1.0328x over previous
#include <cuda_runtime.h>
#include <cstdint>
#include <math.h>

#define D_MODEL 2048
#define N_EXP   64
#define TM      128                 // tokens per CTA
#define KB      32                  // K elems per stage
#define NSTG    (D_MODEL / KB)      // 64
#define THREADS 128
#define XPITCH  36                  // floats; bank-perm pitch
#define WPITCH  36
#define LPITCH  68

#define XS_BYTES (TM * XPITCH * 4)        // 18432
#define WS_BYTES (N_EXP * WPITCH * 4)     // 9216
#define WS_OFF   (2 * XS_BYTES)           // 36864
#define BIAS_OFF (WS_OFF + 2 * WS_BYTES)  // 55296
#define SMEM_DYN (BIAS_OFF + 256)

__device__ __forceinline__ uint32_t smem_u32(const void* p) {
    uint32_t a;
    asm("{ .reg .u64 t; cvta.to.shared.u64 t, %1; cvt.u32.u64 %0, t; }" : "=r"(a) : "l"(p));
    return a;
}
__device__ __forceinline__ void cp16(uint32_t dst, const float* src) {
    asm volatile("cp.async.cg.shared.global [%0], [%1], 16;" :: "r"(dst), "l"(src) : "memory");
}
#define CP_COMMIT() asm volatile("cp.async.commit_group;" ::: "memory")
#define CP_WAIT(n)  asm volatile("cp.async.wait_group %0;" :: "n"(n) : "memory")

__device__ __forceinline__ uint32_t tf32_of(float f) {
    uint32_t r;
    asm("cvt.rna.tf32.f32 %0, %1;" : "=r"(r) : "f"(f));
    return r;
}
// D = A*B + C  (D and C distinct register sets allowed)
__device__ __forceinline__ void mma_dc(float& d0, float& d1, float& d2, float& d3,
                                       uint32_t a0, uint32_t a1, uint32_t a2, uint32_t a3,
                                       uint32_t b0, uint32_t b1,
                                       float c0, float c1, float c2, float c3) {
    asm volatile("mma.sync.aligned.m16n8k8.row.col.f32.tf32.tf32.f32 "
                 "{%0,%1,%2,%3},{%4,%5,%6,%7},{%8,%9},{%10,%11,%12,%13};"
                 : "=f"(d0), "=f"(d1), "=f"(d2), "=f"(d3)
                 : "r"(a0), "r"(a1), "r"(a2), "r"(a3), "r"(b0), "r"(b1),
                   "f"(c0), "f"(c1), "f"(c2), "f"(c3));
}
__device__ __forceinline__ void mma_acc(float& d0, float& d1, float& d2, float& d3,
                                        uint32_t a0, uint32_t a1, uint32_t a2, uint32_t a3,
                                        uint32_t b0, uint32_t b1) {
    asm volatile("mma.sync.aligned.m16n8k8.row.col.f32.tf32.tf32.f32 "
                 "{%0,%1,%2,%3},{%4,%5,%6,%7},{%8,%9},{%0,%1,%2,%3};"
                 : "+f"(d0), "+f"(d1), "+f"(d2), "+f"(d3)
                 : "r"(a0), "r"(a1), "r"(a2), "r"(a3), "r"(b0), "r"(b1));
}

__global__ __launch_bounds__(THREADS)
void router_hmma(const float* __restrict__ x, const float* __restrict__ W,
                 const float* __restrict__ bias, float* __restrict__ out, int T)
{
    extern __shared__ float smf[];
    const uint32_t sbase = smem_u32(smf);

    const int tid  = threadIdx.x;
    const int wid  = tid >> 5;
    const int lane = tid & 31;
    const int g    = lane >> 2;     // fragment group row
    const int c    = lane & 3;      // fragment group col
    const int wm   = wid * 32;      // warp's first token within CTA tile
    const int t0   = blockIdx.x * TM;

    if (tid < N_EXP) smf[BIAS_OFF / 4 + tid] = bias[tid];

    auto load_stage = [&](int s, int buf) {
        const int kofs = s * KB;
        {
            const uint32_t dst0 = sbase + buf * XS_BYTES + (uint32_t)tid * (XPITCH * 4);
            const float* src0 = x + (size_t)(t0 + tid) * D_MODEL + kofs;
#pragma unroll
            for (int ch = 0; ch < 8; ++ch)
                cp16(dst0 + ch * 16, src0 + ch * 4);
        }
        {
            const int row = tid >> 1;
            const int cb  = (tid & 1) * 4;
            const uint32_t dst0 = sbase + WS_OFF + buf * WS_BYTES
                                + (uint32_t)row * (WPITCH * 4) + cb * 16;
            const float* src0 = W + (size_t)row * D_MODEL + kofs + cb * 4;
#pragma unroll
            for (int ch = 0; ch < 4; ++ch)
                cp16(dst0 + ch * 16, src0 + ch * 4);
        }
    };

    float master[2][8][4];
    float stageC[2][8][4];
#pragma unroll
    for (int mb = 0; mb < 2; ++mb)
#pragma unroll
        for (int nb = 0; nb < 8; ++nb)
#pragma unroll
            for (int q = 0; q < 4; ++q) master[mb][nb][q] = 0.0f;

    load_stage(0, 0); CP_COMMIT();
    load_stage(1, 1); CP_COMMIT();

#pragma unroll 1
    for (int s = 0; s < NSTG; ++s) {
        if (s + 1 < NSTG) { CP_WAIT(1); } else { CP_WAIT(0); }
        __syncthreads();

        const float* xb = smf + (size_t)(s & 1) * (XS_BYTES / 4);
        const float* wb = smf + WS_OFF / 4 + (size_t)(s & 1) * (WS_BYTES / 4);

#pragma unroll
        for (int k0 = 0; k0 < KB; k0 += 8) {
            // A fragments for this k-chunk (2 m-blocks), split on the fly
            uint32_t ahi[2][4], alo[2][4];
#pragma unroll
            for (int mb = 0; mb < 2; ++mb) {
                const int r0 = wm + mb * 16 + g;
#pragma unroll
                for (int q = 0; q < 4; ++q) {
                    const int row = r0 + (q & 1) * 8;
                    const int col = k0 + c + ((q >> 1) * 4);
                    const float v = xb[row * XPITCH + col];
                    const uint32_t h = tf32_of(v);
                    ahi[mb][q] = h;
                    alo[mb][q] = tf32_of(v - __uint_as_float(h));
                }
            }
#pragma unroll
            for (int nb = 0; nb < 8; ++nb) {
                // B fragment for this n-block
                uint32_t bhi[2], blo[2];
#pragma unroll
                for (int q = 0; q < 2; ++q) {
                    const float v = wb[(nb * 8 + g) * WPITCH + k0 + c + q * 4];
                    const uint32_t h = tf32_of(v);
                    bhi[q] = h;
                    blo[q] = tf32_of(v - __uint_as_float(h));
                }
#pragma unroll
                for (int mb = 0; mb < 2; ++mb) {
                    float* sc = stageC[mb][nb];
                    if (k0 == 0) {
                        // first chunk of stage: hh overwrites stageC (C = 0)
                        mma_dc(sc[0], sc[1], sc[2], sc[3],
                               ahi[mb][0], ahi[mb][1], ahi[mb][2], ahi[mb][3],
                               bhi[0], bhi[1], 0.0f, 0.0f, 0.0f, 0.0f);
                    } else {
                        mma_acc(sc[0], sc[1], sc[2], sc[3],
                                ahi[mb][0], ahi[mb][1], ahi[mb][2], ahi[mb][3],
                                bhi[0], bhi[1]);
                    }
                    mma_acc(sc[0], sc[1], sc[2], sc[3],
                            ahi[mb][0], ahi[mb][1], ahi[mb][2], ahi[mb][3],
                            blo[0], blo[1]);
                    mma_acc(sc[0], sc[1], sc[2], sc[3],
                            alo[mb][0], alo[mb][1], alo[mb][2], alo[mb][3],
                            bhi[0], bhi[1]);
                }
            }
        }

        // fold stage accumulator into master (RN adds, short RZ chains only)
#pragma unroll
        for (int mb = 0; mb < 2; ++mb)
#pragma unroll
            for (int nb = 0; nb < 8; ++nb)
#pragma unroll
                for (int q = 0; q < 4; ++q)
                    master[mb][nb][q] += stageC[mb][nb][q];

        __syncthreads();                       // all warps done reading buf (s&1)
        if (s + 2 < NSTG) { load_stage(s + 2, s & 1); CP_COMMIT(); }
    }

    // ---- epilogue: dump logits to smem, per-token top-2 + softmax ----
    float* logits = smf;                       // reuse x buffers: 128 x LPITCH
#pragma unroll
    for (int mb = 0; mb < 2; ++mb)
#pragma unroll
        for (int nb = 0; nb < 8; ++nb)
#pragma unroll
            for (int q = 0; q < 4; ++q) {
                const int row = wm + mb * 16 + g + ((q >> 1) * 8);
                const int col = nb * 8 + 2 * c + (q & 1);
                logits[row * LPITCH + col] = master[mb][nb][q];
            }
    __syncthreads();

    {
        const float* lrow   = logits + tid * LPITCH;
        const float* bias_s = smf + BIAS_OFF / 4;
        float m1 = -INFINITY, m2 = -INFINITY;
        int   i1 = 0,         i2 = 0;
        float l[64];
#pragma unroll 8
        for (int e = 0; e < N_EXP; ++e) {
            l[e] = lrow[e] + bias_s[e];
            const float v = l[e];
            if (v > m1) { m2 = m1; i2 = i1; m1 = v; i1 = e; }
            else if (v > m2) { m2 = v; i2 = e; }
        }
        float ssum = 0.0f;
#pragma unroll 8
        for (int e = 0; e < N_EXP; ++e) ssum += __expf(l[e] - m1);
        const float inv = 1.0f / ssum;

        const int tg = t0 + tid;
        out[2 * tg + 0] = (float)i1;
        out[2 * tg + 1] = (float)i2;
        out[(size_t)2 * T + 2 * tg + 0] = inv;
        out[(size_t)2 * T + 2 * tg + 1] = __expf(m2 - m1) * inv;
    }
}

extern "C" void kernel_launch(void* const* d_in, const int* in_sizes, int n_in,
                              void* d_out, int out_size)
{
    const float* x = (const float*)d_in[0];
    const float* W = (const float*)d_in[1];
    const float* b = (const float*)d_in[2];
    float* out = (float*)d_out;

    const int T = in_sizes[0] / D_MODEL;   // 32768
    static int attr_done = 0;
    if (!attr_done) {
        cudaFuncSetAttribute(router_hmma, cudaFuncAttributeMaxDynamicSharedMemorySize, SMEM_DYN);
        attr_done = 1;
    }
    router_hmma<<<T / TM, THREADS, SMEM_DYN>>>(x, W, b, out, T);
}

// round 7
// speedup vs baseline: 1.0481x; 1.0148x over previous
#include <cuda_runtime.h>
#include <cstdint>
#include <math.h>

#define D_MODEL 2048
#define N_EXP   64
#define TM      128                 // tokens per CTA
#define KB      32                  // K elems per stage
#define NSTG    (D_MODEL / KB)      // 64
#define THREADS 256
#define XPITCH  36                  // floats per x row
#define WPITCH  36                  // float2 pairs per W row
#define LPITCH  68

#define XS_BYTES 18432              // 128*36*4, per buffer
#define WS_BYTES 18432              // 64*36*8 (hi/lo pairs), per buffer
#define WOFF     (2 * XS_BYTES)     // 36864
#define BIAS_OFF (WOFF + 2 * WS_BYTES)   // 73728
#define SMEM_DYN (BIAS_OFF + 256)

__device__ float2 g_wint[N_EXP * D_MODEL];   // interleaved (hi, lo) tf32 pairs

__device__ __forceinline__ uint32_t smem_u32(const void* p) {
    uint32_t a;
    asm("{ .reg .u64 t; cvta.to.shared.u64 t, %1; cvt.u32.u64 %0, t; }" : "=r"(a) : "l"(p));
    return a;
}
__device__ __forceinline__ void cp16(uint32_t dst, const float* src) {
    asm volatile("cp.async.cg.shared.global [%0], [%1], 16;" :: "r"(dst), "l"(src) : "memory");
}
#define CP_COMMIT() asm volatile("cp.async.commit_group;" ::: "memory")
#define CP_WAIT(n)  asm volatile("cp.async.wait_group %0;" :: "n"(n) : "memory")

__device__ __forceinline__ uint32_t tf32_of(float f) {
    uint32_t r;
    asm("cvt.rna.tf32.f32 %0, %1;" : "=r"(r) : "f"(f));
    return r;
}
__device__ __forceinline__ void mma_dc(float& d0, float& d1, float& d2, float& d3,
                                       uint32_t a0, uint32_t a1, uint32_t a2, uint32_t a3,
                                       uint32_t b0, uint32_t b1,
                                       float c0, float c1, float c2, float c3) {
    asm volatile("mma.sync.aligned.m16n8k8.row.col.f32.tf32.tf32.f32 "
                 "{%0,%1,%2,%3},{%4,%5,%6,%7},{%8,%9},{%10,%11,%12,%13};"
                 : "=f"(d0), "=f"(d1), "=f"(d2), "=f"(d3)
                 : "r"(a0), "r"(a1), "r"(a2), "r"(a3), "r"(b0), "r"(b1),
                   "f"(c0), "f"(c1), "f"(c2), "f"(c3));
}
__device__ __forceinline__ void mma_acc(float& d0, float& d1, float& d2, float& d3,
                                        uint32_t a0, uint32_t a1, uint32_t a2, uint32_t a3,
                                        uint32_t b0, uint32_t b1) {
    asm volatile("mma.sync.aligned.m16n8k8.row.col.f32.tf32.tf32.f32 "
                 "{%0,%1,%2,%3},{%4,%5,%6,%7},{%8,%9},{%0,%1,%2,%3};"
                 : "+f"(d0), "+f"(d1), "+f"(d2), "+f"(d3)
                 : "r"(a0), "r"(a1), "r"(a2), "r"(a3), "r"(b0), "r"(b1));
}

// ---- prep: split W into interleaved tf32 (hi, lo) pairs ----
__global__ void split_w(const float* __restrict__ W) {
    const int i = blockIdx.x * 256 + threadIdx.x;
    if (i < N_EXP * D_MODEL) {
        const float v = W[i];
        const uint32_t h = tf32_of(v);
        const uint32_t l = tf32_of(v - __uint_as_float(h));
        g_wint[i] = make_float2(__uint_as_float(h), __uint_as_float(l));
    }
}

__global__ __launch_bounds__(THREADS, 2)
void router_hmma(const float* __restrict__ x,
                 const float* __restrict__ bias, float* __restrict__ out, int T)
{
    extern __shared__ float smf[];
    const uint32_t sbase = smem_u32(smf);

    const int tid  = threadIdx.x;
    const int wid  = tid >> 5;      // 0..7
    const int lane = tid & 31;
    const int g    = lane >> 2;
    const int c    = lane & 3;
    const int wm   = wid * 16;      // warp's first token in CTA tile
    const int t0   = blockIdx.x * TM;

    if (tid < N_EXP) smf[BIAS_OFF / 4 + tid] = bias[tid];

    auto load_stage = [&](int s, int buf) {
        const int kofs = s * KB;
        // x: 128 rows x 32 floats; thread -> row tid/2, 4 x 16B
        {
            const int row = tid >> 1;
            const int cs  = (tid & 1) * 4;
            const uint32_t dst0 = sbase + buf * XS_BYTES
                                + (uint32_t)row * (XPITCH * 4) + cs * 16;
            const float* src0 = x + (size_t)(t0 + row) * D_MODEL + kofs + cs * 4;
#pragma unroll
            for (int i = 0; i < 4; ++i) cp16(dst0 + i * 16, src0 + i * 4);
        }
        // W pairs: 64 rows x 32 pairs (256B); thread -> row tid/4, 4 x 16B
        {
            const int row = tid >> 2;
            const int pc  = (tid & 3) * 4;
            const uint32_t dst0 = sbase + WOFF + buf * WS_BYTES
                                + (uint32_t)row * (WPITCH * 8) + pc * 16;
            const float* src0 = (const float*)(g_wint + (size_t)row * D_MODEL + kofs) + pc * 4;
#pragma unroll
            for (int i = 0; i < 4; ++i) cp16(dst0 + i * 16, src0 + i * 4);
        }
    };

    float master[8][4];
    float stageC[8][4];
#pragma unroll
    for (int nb = 0; nb < 8; ++nb)
#pragma unroll
        for (int q = 0; q < 4; ++q) master[nb][q] = 0.0f;

    load_stage(0, 0); CP_COMMIT();
    load_stage(1, 1); CP_COMMIT();

#pragma unroll 1
    for (int s = 0; s < NSTG; ++s) {
        if (s + 1 < NSTG) { CP_WAIT(1); } else { CP_WAIT(0); }
        __syncthreads();

        const float* xb = smf + (size_t)(s & 1) * (XS_BYTES / 4);
        const uint2* wbu = (const uint2*)((const char*)smf + WOFF + (s & 1) * WS_BYTES);

#pragma unroll
        for (int k0 = 0; k0 < KB; k0 += 8) {
            // A fragment (16 tokens), split on the fly
            uint32_t ahi[4], alo[4];
#pragma unroll
            for (int q = 0; q < 4; ++q) {
                const int row = wm + g + (q & 1) * 8;
                const int col = k0 + c + ((q >> 1) * 4);
                const float v = xb[row * XPITCH + col];
                const uint32_t h = tf32_of(v);
                ahi[q] = h;
                alo[q] = tf32_of(v - __uint_as_float(h));
            }
#pragma unroll
            for (int nb = 0; nb < 8; ++nb) {
                const uint2 p0 = wbu[(nb * 8 + g) * WPITCH + k0 + c];
                const uint2 p1 = wbu[(nb * 8 + g) * WPITCH + k0 + c + 4];
                float* sc = stageC[nb];
                if (k0 == 0) {
                    mma_dc(sc[0], sc[1], sc[2], sc[3],
                           ahi[0], ahi[1], ahi[2], ahi[3],
                           p0.x, p1.x, 0.0f, 0.0f, 0.0f, 0.0f);
                } else {
                    mma_acc(sc[0], sc[1], sc[2], sc[3],
                            ahi[0], ahi[1], ahi[2], ahi[3], p0.x, p1.x);
                }
                mma_acc(sc[0], sc[1], sc[2], sc[3],
                        ahi[0], ahi[1], ahi[2], ahi[3], p0.y, p1.y);
                mma_acc(sc[0], sc[1], sc[2], sc[3],
                        alo[0], alo[1], alo[2], alo[3], p0.x, p1.x);
            }
        }

        // fold stage accumulator into master (RN adds, short RZ chains only)
#pragma unroll
        for (int nb = 0; nb < 8; ++nb)
#pragma unroll
            for (int q = 0; q < 4; ++q) master[nb][q] += stageC[nb][q];

        __syncthreads();
        if (s + 2 < NSTG) { load_stage(s + 2, s & 1); CP_COMMIT(); }
    }

    // ---- epilogue: logits to smem (reuse x buffers), top-2 + softmax ----
    float* logits = smf;            // 128 x LPITCH floats = 34816 B < 2*XS_BYTES
#pragma unroll
    for (int nb = 0; nb < 8; ++nb)
#pragma unroll
        for (int q = 0; q < 4; ++q) {
            const int row = wm + g + ((q >> 1) * 8);
            const int col = nb * 8 + 2 * c + (q & 1);
            logits[row * LPITCH + col] = master[nb][q];
        }
    __syncthreads();

    if (tid < TM) {
        const float* lrow   = logits + tid * LPITCH;
        const float* bias_s = smf + BIAS_OFF / 4;
        float m1 = -INFINITY, m2 = -INFINITY;
        int   i1 = 0,         i2 = 0;
        float l[64];
#pragma unroll 8
        for (int e = 0; e < N_EXP; ++e) {
            l[e] = lrow[e] + bias_s[e];
            const float v = l[e];
            if (v > m1) { m2 = m1; i2 = i1; m1 = v; i1 = e; }
            else if (v > m2) { m2 = v; i2 = e; }
        }
        float ssum = 0.0f;
#pragma unroll 8
        for (int e = 0; e < N_EXP; ++e) ssum += __expf(l[e] - m1);
        const float inv = 1.0f / ssum;

        const int tg = t0 + tid;
        out[2 * tg + 0] = (float)i1;
        out[2 * tg + 1] = (float)i2;
        out[(size_t)2 * T + 2 * tg + 0] = inv;
        out[(size_t)2 * T + 2 * tg + 1] = __expf(m2 - m1) * inv;
    }
}

extern "C" void kernel_launch(void* const* d_in, const int* in_sizes, int n_in,
                              void* d_out, int out_size)
{
    const float* x = (const float*)d_in[0];
    const float* W = (const float*)d_in[1];
    const float* b = (const float*)d_in[2];
    float* out = (float*)d_out;

    const int T = in_sizes[0] / D_MODEL;   // 32768
    static int attr_done = 0;
    if (!attr_done) {
        cudaFuncSetAttribute(router_hmma, cudaFuncAttributeMaxDynamicSharedMemorySize, SMEM_DYN);
        attr_done = 1;
    }
    split_w<<<(N_EXP * D_MODEL + 255) / 256, 256>>>(W);
    router_hmma<<<T / TM, THREADS, SMEM_DYN>>>(x, b, out, T);
}